// round 1
// baseline (speedup 1.0000x reference)
#include <cuda_runtime.h>
#include <math.h>

#define BATCH 64
#define NPG 9
#define NTOT (BATCH*NPG)     // 576
#define H 128
#define K1 1801
#define O1 900
#define O2 100
#define ASL 243
#define KSPLIT 8
#define KCHUNK 226           // 7*226 + 219 = 1801

// scratch (no allocation allowed)
__device__ float g_s1_part[KSPLIT * BATCH * O1];
__device__ float g_s1[BATCH * O1];
__device__ float g_s[BATCH * O2];
__device__ float g_Ai[NTOT * H];
__device__ float g_Bj[NTOT * H];
__device__ float g_D[BATCH * H];

// ---------------- GEMM1: s1_part = specs @ W1 (split-K) ----------------
// grid (29, 8), block 256. Block computes all 64 batches x 32 outs over one K chunk.
__global__ void gemm1_kernel(const float* __restrict__ spec, const float* __restrict__ W1) {
    const int t = threadIdx.x;
    const int o = blockIdx.x * 32 + (t & 31);
    const int bg = t >> 5;                 // 0..7 -> batches bg*8 .. bg*8+7
    const int kbeg = blockIdx.y * KCHUNK;
    const int kend = min(kbeg + KCHUNK, K1);

    __shared__ float sp[64][66];           // [batch][kk], padded
    float acc[8];
#pragma unroll
    for (int n = 0; n < 8; n++) acc[n] = 0.f;

    for (int k0 = kbeg; k0 < kend; k0 += 64) {
        const int klen = min(64, kend - k0);
        __syncthreads();
        for (int idx = t; idx < 64 * 64; idx += 256) {
            int bb = idx >> 6, kk = idx & 63;
            sp[bb][kk] = (kk < klen) ? spec[bb * K1 + k0 + kk] : 0.f;
        }
        __syncthreads();
        const float* spb = &sp[bg * 8][0];
#pragma unroll 4
        for (int kk = 0; kk < klen; kk++) {
            float w = (o < O1) ? W1[(k0 + kk) * O1 + o] : 0.f;
#pragma unroll
            for (int n = 0; n < 8; n++)
                acc[n] += spb[n * 66 + kk] * w;
        }
    }
    if (o < O1) {
        float* dst = &g_s1_part[blockIdx.y * (BATCH * O1)];
#pragma unroll
        for (int n = 0; n < 8; n++)
            dst[(bg * 8 + n) * O1 + o] = acc[n];
    }
}

// ---------------- reduce split-K + bias + relu ----------------
__global__ void reduce1_kernel(const float* __restrict__ b1) {
    int i = blockIdx.x * 256 + threadIdx.x;
    if (i < BATCH * O1) {
        float a = b1[i % O1];
#pragma unroll
        for (int c = 0; c < KSPLIT; c++) a += g_s1_part[c * (BATCH * O1) + i];
        g_s1[i] = fmaxf(a, 0.f);
    }
}

// ---------------- GEMM2: s = relu(s1 @ W2 + b2), [64,100] ----------------
__global__ void gemm2_kernel(const float* __restrict__ W2, const float* __restrict__ b2) {
    const int b = blockIdx.x, t = threadIdx.x;   // 128 threads
    __shared__ float sr[O1];
    for (int k = t; k < O1; k += 128) sr[k] = g_s1[b * O1 + k];
    __syncthreads();
    if (t < O2) {
        float a = b2[t];
        for (int k = 0; k < O1; k++) a += sr[k] * W2[k * O2 + t];
        g_s[b * O2 + t] = fmaxf(a, 0.f);
    }
}

// ---------------- Ai/Bj: relu(nf) @ Wa2[:128] and Wa2[128:256] ----------------
// grid 72, block 128; 8 nodes per block
__global__ void ab_kernel(const float* __restrict__ nf, const float* __restrict__ Wa2) {
    const int nb = blockIdx.x * 8;
    const int j = threadIdx.x;
    __shared__ float r[H][8];
#pragma unroll
    for (int n = 0; n < 8; n++) r[j][n] = fmaxf(nf[(nb + n) * H + j], 0.f);
    __syncthreads();
    float a[8], bb[8];
#pragma unroll
    for (int n = 0; n < 8; n++) { a[n] = 0.f; bb[n] = 0.f; }
    for (int k = 0; k < H; k++) {
        float w0 = Wa2[k * H + j];
        float w1 = Wa2[(H + k) * H + j];
        float4 r0 = *(const float4*)&r[k][0];
        float4 r1 = *(const float4*)&r[k][4];
        a[0] += r0.x * w0; a[1] += r0.y * w0; a[2] += r0.z * w0; a[3] += r0.w * w0;
        a[4] += r1.x * w0; a[5] += r1.y * w0; a[6] += r1.z * w0; a[7] += r1.w * w0;
        bb[0] += r0.x * w1; bb[1] += r0.y * w1; bb[2] += r0.z * w1; bb[3] += r0.w * w1;
        bb[4] += r1.x * w1; bb[5] += r1.y * w1; bb[6] += r1.z * w1; bb[7] += r1.w * w1;
    }
#pragma unroll
    for (int n = 0; n < 8; n++) {
        g_Ai[(nb + n) * H + j] = a[n];
        g_Bj[(nb + n) * H + j] = bb[n];
    }
}

// ---------------- D = s @ Wa2[256:356], [64,128] ----------------
__global__ void d_kernel(const float* __restrict__ Wa2) {
    const int b = blockIdx.x, t = threadIdx.x;   // 128 threads
    __shared__ float ss[O2];
    if (t < O2) ss[t] = g_s[b * O2 + t];
    __syncthreads();
    float a = 0.f;
    for (int k = 0; k < O2; k++) a += ss[k] * Wa2[(2 * H + k) * H + t];
    g_D[b * H + t] = a;
}

// ---------------- value head ----------------
__global__ void value_kernel(const float* __restrict__ nf,
                             const float* __restrict__ Wv1, const float* __restrict__ bv1,
                             const float* __restrict__ Wv2, const float* __restrict__ bv2,
                             float* __restrict__ out) {
    const int b = blockIdx.x, t = threadIdx.x;   // 128 threads
    __shared__ float x[H + O2];
    __shared__ float hred[64];
    // readout (sum over 9 nodes, no relu)
    float sum = 0.f;
#pragma unroll
    for (int i = 0; i < NPG; i++) sum += nf[(b * NPG + i) * H + t];
    x[t] = sum;
    if (t < O2) x[H + t] = g_s[b * O2 + t];
    __syncthreads();
    if (t < 64) {
        float a = bv1[t];
        for (int k = 0; k < H + O2; k++) a += x[k] * Wv1[k * 64 + t];
        hred[t] = fmaxf(a, 0.f) * Wv2[t];
    }
    __syncthreads();
    if (t == 0) {
        float v = bv2[0];
        for (int k = 0; k < 64; k++) v += hred[k];
        out[BATCH * ASL + b] = v;
    }
}

// ---------------- pair head + gather + softmax ----------------
__global__ void pair_kernel(const float* __restrict__ ba2, const float* __restrict__ Wf,
                            const float* __restrict__ bf, const int* __restrict__ indexmask,
                            const float* __restrict__ mask, float* __restrict__ out) {
    const int b = blockIdx.x, t = threadIdx.x;   // 128 threads, 4 warps
    const int lane = t & 31, w = t >> 5;
    __shared__ float As[NPG][H], Bs[NPG][H], Dc[H], Wfs[H * 3];
    __shared__ float fp[ASL], gbuf[ASL], rbuf[128];

    for (int idx = t; idx < NPG * H; idx += 128) {
        int i = idx >> 7, h = idx & 127;
        As[i][h] = g_Ai[(b * NPG + i) * H + h];
        Bs[i][h] = g_Bj[(b * NPG + i) * H + h];
    }
    Dc[t] = g_D[b * H + t] + ba2[t];
    for (int idx = t; idx < H * 3; idx += 128) Wfs[idx] = Wf[idx];
    __syncthreads();

    for (int p = w; p < NPG * NPG; p += 4) {
        const int i = p / NPG, j = p % NPG;
        float a0 = 0.f, a1 = 0.f, a2 = 0.f;
#pragma unroll
        for (int c = 0; c < 4; c++) {
            int h = c * 32 + lane;
            float hv = fmaxf(As[i][h] + Bs[j][h] + Dc[h], 0.f);
            a0 += hv * Wfs[h * 3 + 0];
            a1 += hv * Wfs[h * 3 + 1];
            a2 += hv * Wfs[h * 3 + 2];
        }
#pragma unroll
        for (int off = 16; off; off >>= 1) {
            a0 += __shfl_down_sync(0xffffffffu, a0, off);
            a1 += __shfl_down_sync(0xffffffffu, a1, off);
            a2 += __shfl_down_sync(0xffffffffu, a2, off);
        }
        if (lane == 0) {
            fp[p * 3 + 0] = a0 + bf[0];
            fp[p * 3 + 1] = a1 + bf[1];
            fp[p * 3 + 2] = a2 + bf[2];
        }
    }
    __syncthreads();

    // gather + softmax over 243
    float m = -INFINITY;
    for (int i = t; i < ASL; i += 128) {
        float v = fp[indexmask[b * ASL + i]] + mask[b * ASL + i];
        gbuf[i] = v;
        m = fmaxf(m, v);
    }
    rbuf[t] = m;
    __syncthreads();
    for (int s = 64; s; s >>= 1) {
        if (t < s) rbuf[t] = fmaxf(rbuf[t], rbuf[t + s]);
        __syncthreads();
    }
    m = rbuf[0];
    __syncthreads();
    float psum = 0.f;
    for (int i = t; i < ASL; i += 128) {
        float e = expf(gbuf[i] - m);
        gbuf[i] = e;
        psum += e;
    }
    rbuf[t] = psum;
    __syncthreads();
    for (int s = 64; s; s >>= 1) {
        if (t < s) rbuf[t] += rbuf[t + s];
        __syncthreads();
    }
    float inv = 1.f / rbuf[0];
    __syncthreads();
    for (int i = t; i < ASL; i += 128) out[b * ASL + i] = gbuf[i] * inv;
}

extern "C" void kernel_launch(void* const* d_in, const int* in_sizes, int n_in,
                              void* d_out, int out_size) {
    const float* nf   = (const float*)d_in[0];
    const float* spec = (const float*)d_in[1];
    // d_in[2] len_vec unused (block structure is known)
    const float* mask = (const float*)d_in[3];
    const int*   imask= (const int*)  d_in[4];
    const float* W1   = (const float*)d_in[5];
    const float* b1   = (const float*)d_in[6];
    const float* W2   = (const float*)d_in[7];
    const float* b2   = (const float*)d_in[8];
    const float* Wv1  = (const float*)d_in[9];
    const float* bv1  = (const float*)d_in[10];
    const float* Wv2  = (const float*)d_in[11];
    const float* bv2  = (const float*)d_in[12];
    const float* Wa2  = (const float*)d_in[13];
    const float* ba2  = (const float*)d_in[14];
    const float* Wf   = (const float*)d_in[15];
    const float* bf   = (const float*)d_in[16];
    float* out = (float*)d_out;

    gemm1_kernel<<<dim3((O1 + 31) / 32, KSPLIT), 256>>>(spec, W1);
    reduce1_kernel<<<(BATCH * O1 + 255) / 256, 256>>>(b1);
    gemm2_kernel<<<BATCH, 128>>>(W2, b2);
    ab_kernel<<<NTOT / 8, 128>>>(nf, Wa2);
    d_kernel<<<BATCH, 128>>>(Wa2);
    value_kernel<<<BATCH, 128>>>(nf, Wv1, bv1, Wv2, bv2, out);
    pair_kernel<<<BATCH, 128>>>(ba2, Wf, bf, imask, mask, out);
}